// round 7
// baseline (speedup 1.0000x reference)
#include <cuda_runtime.h>
#include <cuda_bf16.h>
#include <math.h>
#include <stdint.h>

// Problem dims (fixed by dataset)
constexpr int BATCH = 8192;
constexpr int DIM   = 1024;
constexpr int HID   = 256;
constexpr long long ED = (long long)BATCH * DIM;  // expert stride (floats)

// GEMM1 tiling (mma.sync m16n8k8 tf32, 3x emulation)
constexpr int BM = 64;
constexpr int BN = 128;
constexpr int BK = 32;
constexpr int NT = 8192 / BK;     // 256 k-tiles
constexpr int STAGES = 2;

constexpr int AST = 36;                        // A smem stride (floats), conflict-free
constexpr int A_BYTES  = BM * AST * 4;         // 9216
constexpr int BP_BYTES = BK * 128 * 4;         // 16384 per plane (hi / lo)
constexpr int STAGE_BYTES = A_BYTES + 2 * BP_BYTES;  // 41984
constexpr int SMEM_SZ = STAGES * STAGE_BYTES;        // 83968  -> occ 2

// Scratch
__device__ float g_h[(size_t)BATCH * HID];                  // gelu(cat@W1+b1)
// pre-split W1: [half(2)][colblk(2)][k(8192)][n'(128)], n' XOR-swizzled
__device__ float g_Bs[(size_t)2 * 2 * 8192 * 128];

// ---------------- helpers ----------------
__device__ __forceinline__ void splt(float x, uint32_t& h, uint32_t& l) {
    asm("cvt.rna.tf32.f32 %0, %1;" : "=r"(h) : "f"(x));
    float r = x - __uint_as_float(h);
    asm("cvt.rna.tf32.f32 %0, %1;" : "=r"(l) : "f"(r));
}
__device__ __forceinline__ float gelu_exact(float x) {
    return 0.5f * x * (1.0f + erff(x * 0.70710678118654752f));
}
__device__ __forceinline__ void cpasync16(void* dst, const void* src) {
    uint32_t d;
    asm("{ .reg .u64 t; cvta.to.shared.u64 t, %1; cvt.u32.u64 %0, t; }"
        : "=r"(d) : "l"(dst));
    asm volatile("cp.async.cg.shared.global [%0], [%1], 16;"
                 :: "r"(d), "l"(src) : "memory");
}
__device__ __forceinline__ void mma_tf32(float* c, const uint32_t* a, const uint32_t* b) {
    asm volatile(
        "mma.sync.aligned.m16n8k8.row.col.f32.tf32.tf32.f32 "
        "{%0,%1,%2,%3}, {%4,%5,%6,%7}, {%8,%9}, {%0,%1,%2,%3};"
        : "+f"(c[0]), "+f"(c[1]), "+f"(c[2]), "+f"(c[3])
        : "r"(a[0]), "r"(a[1]), "r"(a[2]), "r"(a[3]), "r"(b[0]), "r"(b[1]));
}

// ---------------- prep: split W1 into tf32 hi/lo planes (XOR layout) ----------------
__global__ void __launch_bounds__(256) prep_w1(const float* __restrict__ W1) {
    const int idx = blockIdx.x * 256 + threadIdx.x;   // 0 .. 2M-1
    const int n = idx & 255;
    const int k = idx >> 8;
    uint32_t h, l;
    splt(W1[idx], h, l);
    const int cb = n >> 7;
    const int nl = n & 127;
    const int np = nl ^ ((k & 3) << 3);
    const size_t base = ((size_t)cb * 8192 + k) * 128 + np;
    const size_t half = (size_t)2 * 8192 * 128;
    g_Bs[base]        = __uint_as_float(h);
    g_Bs[base + half] = __uint_as_float(l);
}

// ---------------- GEMM1: 3xTF32 mma.sync + bias + GELU ----------------
__global__ void __launch_bounds__(256, 2)
gemm1_mma(const float* __restrict__ zs, const float* __restrict__ b1)
{
    extern __shared__ float smem[];
    const int tid  = threadIdx.x;
    const int lane = tid & 31;
    const int wid  = tid >> 5;
    const int wm   = wid & 1;          // 2 warps along M (32 each)
    const int wn   = wid >> 1;         // 4 warps along N (32 each)
    const int brow = blockIdx.y * BM;
    const int bcol = blockIdx.x * BN;
    const int cb   = blockIdx.x;       // col block for pre-split B

    const size_t bhalf = (size_t)2 * 8192 * 128;

    // copy k-tile kt into stage buffer s
    auto copy_tile = [&](int kt, int s) {
        float* As  = smem + (size_t)s * (STAGE_BYTES / 4);
        float* Bsh = As + A_BYTES / 4;
        float* Bsl = Bsh + BP_BYTES / 4;
        const int k0 = kt * BK;
        const int e  = k0 >> 10;
        const float* abase = zs + (size_t)e * ED + (k0 & 1023);
        // A: 64 rows x 32 floats = 512 chunks, 2 per thread
        #pragma unroll
        for (int i = 0; i < 2; i++) {
            const int c  = tid + i * 256;
            const int r  = c >> 3;
            const int kc = c & 7;
            cpasync16(As + r * AST + kc * 4,
                      abase + (size_t)(brow + r) * DIM + kc * 4);
        }
        // B planes: identity copy of pre-swizzled global images
        const float* gb = g_Bs + ((size_t)cb * 8192 + k0) * 128;
        #pragma unroll
        for (int i = 0; i < 4; i++) {
            const int c  = tid + i * 256;       // 1024 chunks per plane
            const int w4 = c * 4;
            cpasync16(Bsh + w4, gb + w4);
            cpasync16(Bsl + w4, gb + bhalf + w4);
        }
        asm volatile("cp.async.commit_group;" ::: "memory");
    };

    float acc[2][4][4];
    #pragma unroll
    for (int i = 0; i < 2; i++)
        #pragma unroll
        for (int j = 0; j < 4; j++)
            #pragma unroll
            for (int q = 0; q < 4; q++) acc[i][j][q] = 0.0f;

    copy_tile(0, 0);
    copy_tile(1, 1);

    const int l4  = lane & 3;
    const int ld4 = lane >> 2;

    for (int kt = 0; kt < NT; kt++) {
        asm volatile("cp.async.wait_group %0;" :: "n"(STAGES - 2) : "memory");
        __syncthreads();

        const float* As  = smem + (size_t)(kt % STAGES) * (STAGE_BYTES / 4);
        const float* Bsh = As + A_BYTES / 4;
        const float* Bsl = Bsh + BP_BYTES / 4;

        #pragma unroll
        for (int k8 = 0; k8 < BK; k8 += 8) {
            // B fragments (pre-split): 4 n-tiles
            uint32_t bh[4][2], bl[4][2];
            #pragma unroll
            for (int nt = 0; nt < 4; nt++) {
                const int np = (wn * 32 + nt * 8 + ld4) ^ (l4 << 3);
                const int r0 = (k8 + l4) * 128 + np;
                bh[nt][0] = __float_as_uint(Bsh[r0]);
                bh[nt][1] = __float_as_uint(Bsh[r0 + 4 * 128]);
                bl[nt][0] = __float_as_uint(Bsl[r0]);
                bl[nt][1] = __float_as_uint(Bsl[r0 + 4 * 128]);
            }
            #pragma unroll
            for (int mt = 0; mt < 2; mt++) {
                const int m = wm * 32 + mt * 16 + ld4;
                uint32_t ah[4], al[4];
                splt(As[m       * AST + k8 + l4],     ah[0], al[0]);
                splt(As[(m + 8) * AST + k8 + l4],     ah[1], al[1]);
                splt(As[m       * AST + k8 + l4 + 4], ah[2], al[2]);
                splt(As[(m + 8) * AST + k8 + l4 + 4], ah[3], al[3]);
                #pragma unroll
                for (int nt = 0; nt < 4; nt++) {
                    mma_tf32(acc[mt][nt], ah, bh[nt]);
                    mma_tf32(acc[mt][nt], ah, bl[nt]);
                    mma_tf32(acc[mt][nt], al, bh[nt]);
                }
            }
        }
        __syncthreads();
        if (kt + 2 < NT) copy_tile(kt + 2, kt % STAGES);
    }

    // epilogue: bias + exact GELU, direct STG
    #pragma unroll
    for (int mt = 0; mt < 2; mt++) {
        const int r0 = brow + wm * 32 + mt * 16 + ld4;
        #pragma unroll
        for (int nt = 0; nt < 4; nt++) {
            const int cg = bcol + wn * 32 + nt * 8 + 2 * l4;
            const float bx = b1[cg], by = b1[cg + 1];
            float2 o0, o1;
            o0.x = gelu_exact(acc[mt][nt][0] + bx);
            o0.y = gelu_exact(acc[mt][nt][1] + by);
            o1.x = gelu_exact(acc[mt][nt][2] + bx);
            o1.y = gelu_exact(acc[mt][nt][3] + by);
            *(float2*)(g_h + (size_t)r0 * HID + cg)       = o0;
            *(float2*)(g_h + (size_t)(r0 + 8) * HID + cg) = o1;
        }
    }
}

// ---------------- gate (GEMM2 + top2 softmax) + combine ----------------
__global__ void __launch_bounds__(256, 1)
gate_combine(const float* __restrict__ W2, const float* __restrict__ b2,
             const float* __restrict__ zs,
             float* __restrict__ fused, float* __restrict__ wout)
{
    const int warp = threadIdx.x >> 5;
    const int lane = threadIdx.x & 31;
    const int row  = blockIdx.x * 8 + warp;

    const float* hrow = g_h + (size_t)row * HID;
    float acc[8] = {0.f, 0.f, 0.f, 0.f, 0.f, 0.f, 0.f, 0.f};
    #pragma unroll
    for (int kk = 0; kk < 8; kk++) {
        const int k = kk * 32 + lane;
        const float hv = hrow[k];
        const float4 wa = *(const float4*)(W2 + (size_t)k * 8);
        const float4 wb = *(const float4*)(W2 + (size_t)k * 8 + 4);
        acc[0] += hv * wa.x; acc[1] += hv * wa.y;
        acc[2] += hv * wa.z; acc[3] += hv * wa.w;
        acc[4] += hv * wb.x; acc[5] += hv * wb.y;
        acc[6] += hv * wb.z; acc[7] += hv * wb.w;
    }
    #pragma unroll
    for (int m = 0; m < 8; m++) {
        #pragma unroll
        for (int s = 16; s > 0; s >>= 1)
            acc[m] += __shfl_xor_sync(0xffffffffu, acc[m], s);
        acc[m] += b2[m];
    }

    // top-2, jax tie-break (lower index wins -> strict >)
    int i1 = 0; float l1 = acc[0];
    #pragma unroll
    for (int m = 1; m < 8; m++) if (acc[m] > l1) { l1 = acc[m]; i1 = m; }
    int i2 = (i1 == 0) ? 1 : 0; float l2 = acc[i2];
    #pragma unroll
    for (int m = 0; m < 8; m++)
        if (m != i1 && m != ((i1 == 0) ? 1 : 0) && acc[m] > l2) { l2 = acc[m]; i2 = m; }

    const float e2  = expf(l2 - l1);
    const float inv = 1.0f / (1.0f + e2);
    const float w1  = inv;
    const float w2v = e2 * inv;

    if (lane < 8)
        wout[(size_t)row * 8 + lane] =
            (lane == i1) ? w1 : ((lane == i2) ? w2v : 0.0f);

    const float4* z1 = (const float4*)(zs + (size_t)i1 * ED + (size_t)row * DIM);
    const float4* z2 = (const float4*)(zs + (size_t)i2 * ED + (size_t)row * DIM);
    float4* fo = (float4*)(fused + (size_t)row * DIM);
    #pragma unroll
    for (int v = 0; v < 8; v++) {
        const int idx = v * 32 + lane;
        const float4 A  = z1[idx];
        const float4 Bv = z2[idx];
        float4 o;
        o.x = w1 * A.x + w2v * Bv.x;
        o.y = w1 * A.y + w2v * Bv.y;
        o.z = w1 * A.z + w2v * Bv.z;
        o.w = w1 * A.w + w2v * Bv.w;
        fo[idx] = o;
    }
}

extern "C" void kernel_launch(void* const* d_in, const int* in_sizes, int n_in,
                              void* d_out, int out_size)
{
    const float* zs = (const float*)d_in[0];
    const float* W1 = (const float*)d_in[1];
    const float* b1 = (const float*)d_in[2];
    const float* W2 = (const float*)d_in[3];
    const float* b2 = (const float*)d_in[4];

    float* out   = (float*)d_out;
    float* fused = out;                        // [B, D]
    float* wout  = out + (size_t)BATCH * DIM;  // [B, M]

    cudaFuncSetAttribute(gemm1_mma, cudaFuncAttributeMaxDynamicSharedMemorySize, SMEM_SZ);

    prep_w1<<<(8192 * 256) / 256, 256>>>(W1);
    gemm1_mma<<<dim3(HID / BN, BATCH / BM), 256, SMEM_SZ>>>(zs, b1);
    gate_combine<<<BATCH / 8, 256>>>(W2, b2, zs, fused, wout);
}